// round 15
// baseline (speedup 1.0000x reference)
#include <cuda_runtime.h>
#include <cuda_bf16.h>
#include <math.h>
#include <stdint.h>

#define NN 10000
#define NE 160000
#define NG 64

__device__ __align__(128) float g_f[68450000];
__device__ double g_d[2048];
__device__ int    g_i[520064];

#define O_EA    0UL
#define O_EB    20480000UL
#define O_H     40960000UL
#define O_X1    44800000UL
#define O_ATTNP 46080000UL
#define O_XC    47360000UL
#define O_XO    48640000UL
#define O_AGGE  49920000UL
#define O_AGGHS 53760000UL
#define O_HM    55040000UL
#define O_LOG   56320000UL
#define O_EATTN 56800000UL
#define O_SSRC  56960000UL
#define O_SDST  56990000UL
#define O_ASUM  57020000UL
#define O_A2    57099152UL
#define O_C2    57099556UL
#define O_B1M   57115924UL
#define O_MUC   57116308UL
#define O_INVC  57116436UL
#define O_MUO   57116564UL
#define O_INVO  57116692UL
#define O_GC    57116820UL
#define O_GO    57125012UL
#define O_IMG   57140000UL
#define O2_LOG   57400000UL
#define O2_SSRC  57880000UL
#define O2_SDST  57910000UL
#define O2_ASUM  57940000UL
#define O2_AGGHS 57970000UL
#define O2_AGGE  59250000UL
#define O2_HM    63090000UL
#define O2_A2    64370000UL
#define O2_C2    64370404UL
#define O2_B1M   64370410UL
#define O2_IMG   64370560UL
#define O2_H     64600000UL
#define DS_EDGEMOM 1536

#define IM_WNH 0
#define IM_WNL 49152
#define IM_WPH 98304
#define IM_WPL 147456
#define IM_WEH 196608
#define IM_WEL 212992

__device__ __forceinline__ uint32_t packsplit(float x, float y, uint32_t& lo) {
    __nv_bfloat162 h = __floats2bfloat162_rn(x, y);
    __nv_bfloat162 l = __floats2bfloat162_rn(x - __low2float(h), y - __high2float(h));
    lo = *(uint32_t*)&l;
    return *(uint32_t*)&h;
}

// -------- CSR --------
__global__ void k_count(const int* __restrict__ col, int* __restrict__ cnt,
                        double* __restrict__ ds) {
    int i = blockIdx.x * blockDim.x + threadIdx.x;
    if (blockIdx.x == 0 && threadIdx.x < 256) ds[threadIdx.x] = 0.0;
    if (i < NE) atomicAdd(&cnt[col[i]], 1);
}
__global__ void k_scan(const int* __restrict__ cnt, int* __restrict__ offs,
                       int* __restrict__ fill, double* __restrict__ ds) {
    __shared__ int sm[1024];
    int t = threadIdx.x;
    ds[256 + t] = 0.0;
    if (t < 768) ds[1280 + t] = 0.0;
    const int per = (NN + 1023) / 1024;
    int b = t * per, e = min(NN, b + per);
    int s = 0;
    for (int i = b; i < e; i++) s += cnt[i];
    sm[t] = s; __syncthreads();
    for (int o = 1; o < 1024; o <<= 1) {
        int v = (t >= o) ? sm[t - o] : 0;
        __syncthreads(); sm[t] += v; __syncthreads();
    }
    int base = (t == 0) ? 0 : sm[t - 1];
    for (int i = b; i < e; i++) { offs[i] = base; fill[i] = base; base += cnt[i]; }
    if (t == 1023) offs[NN] = sm[1023];
}
__global__ void k_fill(const int* __restrict__ col, const int* __restrict__ row,
                       int* __restrict__ fill, int* __restrict__ perm,
                       int* __restrict__ ip, int* __restrict__ rowp) {
    int i = blockIdx.x * blockDim.x + threadIdx.x;
    if (i < NE) {
        int p = atomicAdd(&fill[col[i]], 1);
        perm[p] = i; ip[i] = p; rowp[p] = row[i];
    }
}

// -------- BN stats --------
__global__ void k_colstat(const float* __restrict__ X, int rows, double* __restrict__ sums) {
    int c = threadIdx.x;
    double s = 0, s2 = 0;
    for (int r = blockIdx.x * 8; r < rows; r += gridDim.x * 8) {
        #pragma unroll
        for (int q = 0; q < 8; q++) {
            int rr = r + q;
            float v = (rr < rows) ? X[(size_t)rr * 128 + c] : 0.f;
            s += v; s2 += (double)v * v;
        }
    }
    atomicAdd(&sums[c], s);
    atomicAdd(&sums[128 + c], s2);
}
__global__ void k_edgemom(const float* __restrict__ E4, const float* __restrict__ attn,
                          double* __restrict__ sums) {
    int t = threadIdx.x;
    double sc = 0, sc2 = 0, so = 0, so2 = 0;
    #pragma unroll 4
    for (int r = blockIdx.x; r < NE; r += gridDim.x) {
        float w = attn[r];
        float v = E4[(size_t)r * 128 + t];
        float tc = w * v, to = (1.f - w) * v;
        sc += tc; sc2 += (double)tc * tc;
        so += to; so2 += (double)to * to;
    }
    atomicAdd(&sums[t], sc); atomicAdd(&sums[128 + t], sc2);
    atomicAdd(&sums[256 + t], so); atomicAdd(&sums[384 + t], so2);
}
__global__ void k_edgemomfin(const double* __restrict__ sums, float* __restrict__ muc,
                             float* __restrict__ invc, float* __restrict__ muo,
                             float* __restrict__ invo) {
    int c = threadIdx.x;
    double m = sums[c] / NE, v = sums[128 + c] / NE - m * m;
    muc[c] = (float)m; invc[c] = (float)rsqrt(v + 1e-5);
    m = sums[256 + c] / NE; v = sums[384 + c] / NE - m * m;
    muo[c] = (float)m; invo[c] = (float)rsqrt(v + 1e-5);
}

// -------- B image prep --------
__global__ void k_bprepW(const float* __restrict__ Wn, uint32_t* __restrict__ bh,
                         uint32_t* __restrict__ bl) {
    int i = blockIdx.x * blockDim.x + threadIdx.x;
    if (i >= 64 * 384) return;
    int k2 = i / 384, n = i % 384;
    float v0 = Wn[(size_t)(2 * k2) * 384 + n];
    float v1 = Wn[(size_t)(2 * k2 + 1) * 384 + n];
    uint32_t lo; uint32_t hi = packsplit(v0, v1, lo);
    bh[i] = hi; bl[i] = lo;
}

__global__ void k_wprep(const float* __restrict__ We, const float* __restrict__ b1,
                        const float* __restrict__ a2, int fe, int need_em,
                        float* __restrict__ A2, float* __restrict__ C2,
                        float* __restrict__ B1M, uint32_t* __restrict__ wph,
                        uint32_t* __restrict__ wpl, uint32_t* __restrict__ weh,
                        uint32_t* __restrict__ wel) {
    int i = blockIdx.x * blockDim.x + threadIdx.x;
    if (i < fe * 3) {
        int f = i / 3, h = i % 3;
        float s = 0;
        for (int d = 0; d < 128; d++) s += We[(size_t)(f * 3 + h) * 128 + d] * a2[h * 128 + d];
        A2[i] = s;
    }
    if (i < 3) {
        float s = 0;
        for (int d = 0; d < 128; d++) s += b1[i * 128 + d] * a2[i * 128 + d];
        C2[i] = s;
    }
    if (i < 128) B1M[i] = (b1[i] + b1[128 + i] + b1[256 + i]) * (1.f / 3.f);
    int tot = (3 * fe / 2) * 128;
    if (i < tot) {
        int k2 = i / 128, d = i % 128;
        int ka = 2 * k2, kb = 2 * k2 + 1;
        float v0 = We[(size_t)((ka % fe) * 3 + (ka / fe)) * 128 + d];
        float v1 = We[(size_t)((kb % fe) * 3 + (kb / fe)) * 128 + d];
        uint32_t lo; uint32_t hi = packsplit(v0, v1, lo);
        wph[i] = hi; wpl[i] = lo;
    }
    if (need_em && i < (fe / 2) * 128) {
        int k2 = i / 128, d = i % 128;
        float v0 = (We[(size_t)(2 * k2 * 3) * 128 + d] + We[(size_t)(2 * k2 * 3 + 1) * 128 + d] +
                    We[(size_t)(2 * k2 * 3 + 2) * 128 + d]) * (1.f / 3.f);
        float v1 = (We[(size_t)((2 * k2 + 1) * 3) * 128 + d] + We[(size_t)((2 * k2 + 1) * 3 + 1) * 128 + d] +
                    We[(size_t)((2 * k2 + 1) * 3 + 2) * 128 + d]) * (1.f / 3.f);
        uint32_t lo; uint32_t hi = packsplit(v0, v1, lo);
        weh[i] = hi; wel[i] = lo;
    }
}

// -------- node scores --------
__global__ void k_nodescore(const float* __restrict__ H, const float* __restrict__ a,
                            float* __restrict__ ssrc, float* __restrict__ sdst,
                            float* __restrict__ hm) {
    int n = blockIdx.x * (blockDim.x >> 5) + (threadIdx.x >> 5);
    int lane = threadIdx.x & 31;
    if (n >= NN) return;
    const float* hp = H + (size_t)n * 384;
    float s[6] = {0, 0, 0, 0, 0, 0};
    #pragma unroll
    for (int q = 0; q < 4; q++) {
        int f = lane + q * 32;
        float h0 = hp[f], h1 = hp[128 + f], h2 = hp[256 + f];
        hm[(size_t)n * 128 + f] = (h0 + h1 + h2) * (1.f / 3.f);
        s[0] += h0 * a[f];       s[1] += h1 * a[128 + f]; s[2] += h2 * a[256 + f];
        s[3] += h0 * a[384 + f]; s[4] += h1 * a[512 + f]; s[5] += h2 * a[640 + f];
    }
    #pragma unroll
    for (int o = 16; o > 0; o >>= 1)
        #pragma unroll
        for (int q = 0; q < 6; q++) s[q] += __shfl_xor_sync(0xffffffffu, s[q], o);
    if (lane < 3) {
        ssrc[n * 3 + lane] = s[lane];
        sdst[n * 3 + lane] = s[3 + lane];
    }
}

// -------- edge logits --------
__global__ void k_edgelogit(const float* __restrict__ ef, int fe,
                            const int* __restrict__ row, const int* __restrict__ colv,
                            const int* __restrict__ ip,
                            const float* __restrict__ ssrc, const float* __restrict__ sdst,
                            const float* __restrict__ A2, const float* __restrict__ C2,
                            const float* __restrict__ attn, int oneminus,
                            const float* __restrict__ mu, const float* __restrict__ inv,
                            float* __restrict__ logits, float* __restrict__ eattn,
                            float* __restrict__ attnp, int do_attn) {
    int gw = (blockIdx.x * blockDim.x + threadIdx.x) >> 5;
    int lane = threadIdx.x & 31;
    if (gw >= NE) return;
    float w = 1.f;
    if (attn) { w = attn[gw]; if (oneminus) w = 1.f - w; }
    float p0 = 0, p1 = 0, p2 = 0;
    if (fe == 128) {
        int i = lane * 4;
        float4 v4 = *(const float4*)&ef[(size_t)gw * 128 + i];
        float v[4] = {v4.x, v4.y, v4.z, v4.w};
        #pragma unroll
        for (int q = 0; q < 4; q++) {
            float v1 = v[q];
            if (mu) v1 = (w * v1 - mu[i + q]) * inv[i + q] + 1e-4f;
            p0 += v1 * A2[(i + q) * 3 + 0];
            p1 += v1 * A2[(i + q) * 3 + 1];
            p2 += v1 * A2[(i + q) * 3 + 2];
        }
    } else {
        for (int i = lane; i < fe; i += 32) {
            float v = ef[(size_t)gw * fe + i];
            if (mu) v = (w * v - mu[i]) * inv[i] + 1e-4f;
            p0 += v * A2[i * 3 + 0]; p1 += v * A2[i * 3 + 1]; p2 += v * A2[i * 3 + 2];
        }
    }
    #pragma unroll
    for (int o = 16; o > 0; o >>= 1) {
        p0 += __shfl_down_sync(0xffffffffu, p0, o);
        p1 += __shfl_down_sync(0xffffffffu, p1, o);
        p2 += __shfl_down_sync(0xffffffffu, p2, o);
    }
    if (lane == 0) {
        int r = row[gw], c = colv[gw];
        float l0 = ssrc[r * 3 + 0] + sdst[c * 3 + 0] + p0 + C2[0];
        float l1 = ssrc[r * 3 + 1] + sdst[c * 3 + 1] + p1 + C2[1];
        float l2 = ssrc[r * 3 + 2] + sdst[c * 3 + 2] + p2 + C2[2];
        l0 = l0 > 0.f ? l0 : 0.2f * l0;
        l1 = l1 > 0.f ? l1 : 0.2f * l1;
        l2 = l2 > 0.f ? l2 : 0.2f * l2;
        int pos = ip[gw];
        logits[pos * 3 + 0] = l0; logits[pos * 3 + 1] = l1; logits[pos * 3 + 2] = l2;
        if (do_attn) {
            float m = (l0 + l1 + l2) * (1.f / 3.f);
            float at = 1.f / (1.f + expf(-m));
            eattn[gw] = at;
            attnp[pos] = at;
        }
    }
}

// -------- per-node softmax + aggregation --------
__global__ void k_nodeagg(const int* __restrict__ offs, const int* __restrict__ perm,
                          const int* __restrict__ rowp, float* __restrict__ L,
                          const float* __restrict__ H, const float* __restrict__ ef, int fe,
                          const float* __restrict__ attnp, int oneminus,
                          const float* __restrict__ mu, const float* __restrict__ inv,
                          float* __restrict__ agghs, float* __restrict__ aggE,
                          float* __restrict__ asum) {
    __shared__ float red[3][128];
    __shared__ float sval[6];
    int n = blockIdx.x, t = threadIdx.x;
    int s = offs[n], e = offs[n + 1];

    float mx0 = -1e30f, mx1 = -1e30f, mx2 = -1e30f;
    for (int j = s + t; j < e; j += 128) {
        mx0 = fmaxf(mx0, L[j * 3 + 0]);
        mx1 = fmaxf(mx1, L[j * 3 + 1]);
        mx2 = fmaxf(mx2, L[j * 3 + 2]);
    }
    red[0][t] = mx0; red[1][t] = mx1; red[2][t] = mx2;
    __syncthreads();
    for (int o = 64; o > 0; o >>= 1) {
        if (t < o) {
            red[0][t] = fmaxf(red[0][t], red[0][t + o]);
            red[1][t] = fmaxf(red[1][t], red[1][t + o]);
            red[2][t] = fmaxf(red[2][t], red[2][t + o]);
        }
        __syncthreads();
    }
    if (t < 3) sval[t] = red[t][0];
    __syncthreads();
    float m0 = sval[0], m1 = sval[1], m2 = sval[2];

    float sm0 = 0, sm1 = 0, sm2 = 0;
    for (int j = s + t; j < e; j += 128) {
        float w0 = expf(L[j * 3 + 0] - m0);
        float w1 = expf(L[j * 3 + 1] - m1);
        float w2 = expf(L[j * 3 + 2] - m2);
        L[j * 3 + 0] = w0; L[j * 3 + 1] = w1; L[j * 3 + 2] = w2;
        sm0 += w0; sm1 += w1; sm2 += w2;
    }
    red[0][t] = sm0; red[1][t] = sm1; red[2][t] = sm2;
    __syncthreads();
    for (int o = 64; o > 0; o >>= 1) {
        if (t < o) {
            red[0][t] += red[0][t + o];
            red[1][t] += red[1][t + o];
            red[2][t] += red[2][t + o];
        }
        __syncthreads();
    }
    if (t < 3) sval[t] = 1.f / (red[t][0] + 1e-16f);
    if (t >= 3 && t < 6) sval[t] = red[t - 3][0];
    __syncthreads();
    float i0 = sval[0], i1 = sval[1], i2 = sval[2];
    if (t == 0) {
        asum[n * 3 + 0] = sval[3] * i0;
        asum[n * 3 + 1] = sval[4] * i1;
        asum[n * 3 + 2] = sval[5] * i2;
    }

    float a_hs = 0, aE0 = 0, aE1 = 0, aE2 = 0;
    for (int j0 = s; j0 < e; j0 += 4) {
        int cnt = e - j0; if (cnt > 4) cnt = 4;
        int r[4], id[4];
        float w0[4], w1[4], w2[4], ww[4];
        #pragma unroll
        for (int q = 0; q < 4; q++) {
            if (q < cnt) {
                r[q] = rowp[j0 + q];
                w0[q] = L[(j0 + q) * 3 + 0] * i0;
                w1[q] = L[(j0 + q) * 3 + 1] * i1;
                w2[q] = L[(j0 + q) * 3 + 2] * i2;
                id[q] = perm[j0 + q];
                if (mu) { ww[q] = attnp[j0 + q]; if (oneminus) ww[q] = 1.f - ww[q]; }
            }
        }
        #pragma unroll
        for (int q = 0; q < 4; q++) {
            if (q < cnt) {
                const float* hp = &H[(size_t)r[q] * 384];
                a_hs += w0[q] * hp[t] + w1[q] * hp[128 + t] + w2[q] * hp[256 + t];
                if (t < fe) {
                    float v = ef[(size_t)id[q] * fe + t];
                    if (mu) v = (ww[q] * v - mu[t]) * inv[t] + 1e-4f;
                    aE0 += w0[q] * v; aE1 += w1[q] * v; aE2 += w2[q] * v;
                }
            }
        }
    }
    agghs[(size_t)n * 128 + t] = a_hs;
    if (t < fe) {
        aggE[(size_t)n * 3 * fe + 0 * fe + t] = aE0;
        aggE[(size_t)n * 3 * fe + 1 * fe + t] = aE1;
        aggE[(size_t)n * 3 * fe + 2 * fe + t] = aE2;
    }
}

// -------- bf16-split tensor-core GEMM (R13 single-buffer + optional out-stats) --------
__device__ __forceinline__ void mma_bf(float c[4], const uint32_t a[4], const uint32_t b[2]) {
    asm volatile(
        "mma.sync.aligned.m16n8k16.row.col.f32.bf16.bf16.f32 "
        "{%0,%1,%2,%3},{%4,%5,%6,%7},{%8,%9},{%0,%1,%2,%3};\n"
        : "+f"(c[0]), "+f"(c[1]), "+f"(c[2]), "+f"(c[3])
        : "r"(a[0]), "r"(a[1]), "r"(a[2]), "r"(a[3]), "r"(b[0]), "r"(b[1]));
}

__global__ void __launch_bounds__(256, 2)
k_gemm(const float* __restrict__ A, const uint32_t* __restrict__ bhg,
       const uint32_t* __restrict__ blg,
       float* __restrict__ C, int M, int N, int K, int mode,
       const float* __restrict__ p0, const float* __restrict__ p1,
       const float* __restrict__ p2,
       const int* __restrict__ ridx, const int* __restrict__ cidx,
       const double* __restrict__ dsums, int bnrows, double* __restrict__ osums) {
    __shared__ uint32_t Ah[8][136], Al[8][136], Bh[8][136], Bl[8][136];
    __shared__ float bnmu[128], bninv[128];
    __shared__ float st_s[128], st_s2[128];
    int tid = threadIdx.x, wid = tid >> 5, lane = tid & 31;
    int g = lane >> 2, tk = lane & 3;
    int bm = blockIdx.y * 128, bn = blockIdx.x * 128;
    int wm = (wid & 1) * 64, wn = (wid >> 1) * 32;

    if (tid < 128) {
        if (osums) { st_s[tid] = 0.f; st_s2[tid] = 0.f; }
        if (dsums) {
            double m = dsums[tid] / bnrows;
            double v = dsums[128 + tid] / bnrows - m * m;
            bnmu[tid] = (float)m;
            bninv[tid] = (float)rsqrt(v + 1e-5);
        }
    }
    if (dsums || osums) __syncthreads();

    float acc[4][4][4];
    #pragma unroll
    for (int i = 0; i < 4; i++)
        #pragma unroll
        for (int j = 0; j < 4; j++)
            #pragma unroll
            for (int q = 0; q < 4; q++) acc[i][j][q] = 0.f;

    int bk2 = tid >> 5, bn4 = (tid & 31) * 4;

    for (int k0 = 0; k0 < K; k0 += 16) {
        #pragma unroll
        for (int rep = 0; rep < 2; rep++) {
            int idx = tid + rep * 256;
            int r = idx >> 2, kq = (idx & 3) * 4;
            float4 av = make_float4(0.f, 0.f, 0.f, 0.f);
            if (bm + r < M) {
                av = *(const float4*)&A[(size_t)(bm + r) * K + k0 + kq];
                if (dsums) {
                    int kk = k0 + kq;
                    av.x = (av.x - bnmu[kk + 0]) * bninv[kk + 0] + 1e-4f;
                    av.y = (av.y - bnmu[kk + 1]) * bninv[kk + 1] + 1e-4f;
                    av.z = (av.z - bnmu[kk + 2]) * bninv[kk + 2] + 1e-4f;
                    av.w = (av.w - bnmu[kk + 3]) * bninv[kk + 3] + 1e-4f;
                }
            }
            uint32_t lo;
            int k2 = kq >> 1;
            Ah[k2][r] = packsplit(av.x, av.y, lo); Al[k2][r] = lo;
            Ah[k2 + 1][r] = packsplit(av.z, av.w, lo); Al[k2 + 1][r] = lo;
        }
        {
            size_t gi = (size_t)((k0 >> 1) + bk2) * N + bn + bn4;
            uint4 hv = *(const uint4*)&bhg[gi];
            uint4 lv = *(const uint4*)&blg[gi];
            *(uint4*)&Bh[bk2][bn4] = hv;
            *(uint4*)&Bl[bk2][bn4] = lv;
        }
        __syncthreads();

        uint32_t bh[4][2], bl[4][2];
        #pragma unroll
        for (int nf = 0; nf < 4; nf++) {
            int nc = wn + nf * 8 + g;
            bh[nf][0] = Bh[tk][nc];     bh[nf][1] = Bh[tk + 4][nc];
            bl[nf][0] = Bl[tk][nc];     bl[nf][1] = Bl[tk + 4][nc];
        }
        #pragma unroll
        for (int mf = 0; mf < 4; mf++) {
            int mr = wm + mf * 16 + g;
            uint32_t ah[4], al[4];
            ah[0] = Ah[tk][mr];     ah[1] = Ah[tk][mr + 8];
            ah[2] = Ah[tk + 4][mr]; ah[3] = Ah[tk + 4][mr + 8];
            al[0] = Al[tk][mr];     al[1] = Al[tk][mr + 8];
            al[2] = Al[tk + 4][mr]; al[3] = Al[tk + 4][mr + 8];
            #pragma unroll
            for (int nf = 0; nf < 4; nf++) {
                mma_bf(acc[mf][nf], ah, bh[nf]);
                mma_bf(acc[mf][nf], ah, bl[nf]);
                mma_bf(acc[mf][nf], al, bh[nf]);
            }
        }
        __syncthreads();
    }

    #pragma unroll
    for (int mf = 0; mf < 4; mf++) {
        int r0 = bm + wm + mf * 16 + g;
        #pragma unroll
        for (int half = 0; half < 2; half++) {
            int m = half ? (r0 + 8) : r0;
            if (m >= M) continue;
            int rr = 0, cc = 0;
            if (mode == 2) { rr = ridx[m]; cc = cidx[m]; }
            #pragma unroll
            for (int nf = 0; nf < 4; nf++) {
                int n0 = bn + wn + nf * 8 + tk * 2;
                float v0 = acc[mf][nf][half * 2 + 0];
                float v1 = acc[mf][nf][half * 2 + 1];
                if (mode == 0) {
                    v0 += p0[n0]; v1 += p0[n0 + 1];
                } else if (mode == 1) {
                    float s0 = p1[m * 3 + 0], s1 = p1[m * 3 + 1], s2 = p1[m * 3 + 2];
                    v0 += p0[(size_t)m * 128 + n0];
                    v0 += s0 * p2[n0] + s1 * p2[128 + n0] + s2 * p2[256 + n0];
                    v0 = fmaxf(v0 * (1.f / 3.f), 0.f);
                    v1 += p0[(size_t)m * 128 + n0 + 1];
                    v1 += s0 * p2[n0 + 1] + s1 * p2[128 + n0 + 1] + s2 * p2[256 + n0 + 1];
                    v1 = fmaxf(v1 * (1.f / 3.f), 0.f);
                } else {
                    v0 += p0[n0] + p1[(size_t)rr * 128 + n0] + p1[(size_t)cc * 128 + n0];
                    v0 = fmaxf(v0, 0.f);
                    v1 += p0[n0 + 1] + p1[(size_t)rr * 128 + n0 + 1] + p1[(size_t)cc * 128 + n0 + 1];
                    v1 = fmaxf(v1, 0.f);
                }
                if (osums) {
                    atomicAdd(&st_s[n0], v0); atomicAdd(&st_s2[n0], v0 * v0);
                    atomicAdd(&st_s[n0 + 1], v1); atomicAdd(&st_s2[n0 + 1], v1 * v1);
                }
                *(float2*)&C[(size_t)m * N + n0] = make_float2(v0, v1);
            }
        }
    }
    if (osums) {
        __syncthreads();
        if (tid < 128) {
            atomicAdd(&osums[tid], (double)st_s[tid]);
            atomicAdd(&osums[128 + tid], (double)st_s2[tid]);
        }
    }
}

// -------- node attention split (+ fused column stats for XC/XO) --------
__global__ void k_natt(const float* __restrict__ x, const float* __restrict__ W,
                       const float* __restrict__ b, float* __restrict__ xc,
                       float* __restrict__ xo, double* __restrict__ sc,
                       double* __restrict__ so) {
    __shared__ float cs[128], cs2[128], os[128], os2[128];
    int t = threadIdx.x;
    if (t < 128) { cs[t] = 0.f; cs2[t] = 0.f; os[t] = 0.f; os2[t] = 0.f; }
    __syncthreads();
    int n = blockIdx.x * (blockDim.x >> 5) + (t >> 5);
    int lane = t & 31;
    if (n < NN) {
        float d0 = 0, d1 = 0;
        for (int i = lane; i < 128; i += 32) {
            float v = x[(size_t)n * 128 + i];
            d0 += v * W[i * 2 + 0]; d1 += v * W[i * 2 + 1];
        }
        #pragma unroll
        for (int o = 16; o > 0; o >>= 1) {
            d0 += __shfl_xor_sync(0xffffffffu, d0, o);
            d1 += __shfl_xor_sync(0xffffffffu, d1, o);
        }
        d0 += b[0]; d1 += b[1];
        float mx = fmaxf(d0, d1);
        float e0 = expf(d0 - mx), e1 = expf(d1 - mx);
        float inv = 1.f / (e0 + e1);
        float n0 = e0 * inv, n1 = e1 * inv;
        for (int i = lane; i < 128; i += 32) {
            float v = x[(size_t)n * 128 + i];
            float vc = n0 * v, vo = n1 * v;
            xc[(size_t)n * 128 + i] = vc;
            xo[(size_t)n * 128 + i] = vo;
            atomicAdd(&cs[i], vc); atomicAdd(&cs2[i], vc * vc);
            atomicAdd(&os[i], vo); atomicAdd(&os2[i], vo * vo);
        }
    }
    __syncthreads();
    if (t < 128) {
        atomicAdd(&sc[t], (double)cs[t]);
        atomicAdd(&sc[128 + t], (double)cs2[t]);
        atomicAdd(&so[t], (double)os[t]);
        atomicAdd(&so[128 + t], (double)os2[t]);
    }
}

__global__ void k_segsum(const float* __restrict__ x, const int* __restrict__ batch,
                         float* __restrict__ g) {
    int i = blockIdx.x * blockDim.x + threadIdx.x;
    if (i < NN * 128) {
        int n = i >> 7;
        atomicAdd(&g[(size_t)batch[n] * 128 + (i & 127)], x[i]);
    }
}

__global__ void k_readout(const float* __restrict__ gc, const float* __restrict__ go,
                          const float* __restrict__ W1s, const float* __restrict__ b1s,
                          const float* __restrict__ W2s, const float* __restrict__ b2s,
                          float* __restrict__ out) {
    int which = blockIdx.x, t = threadIdx.x;
    __shared__ float M[64][129];
    __shared__ float Z[64][12];
    const float* W1 = W1s + which * 16384;
    const float* B1 = b1s + which * 128;
    const float* W2 = W2s + which * 1280;
    const float* B2 = b2s + which * 10;

    double s = 0, s2 = 0;
    for (int r = 0; r < 64; r++) {
        float v = (which == 0) ? gc[r * 128 + t]
                : (which == 1) ? go[r * 128 + t]
                               : gc[r * 128 + t] + go[r * 128 + t];
        s += v; s2 += (double)v * v;
    }
    double mud = s / 64.0;
    float mu = (float)mud;
    float iv = (float)rsqrt(s2 / 64.0 - mud * mud + 1e-5);
    for (int r = 0; r < 64; r++) {
        float v = (which == 0) ? gc[r * 128 + t]
                : (which == 1) ? go[r * 128 + t]
                               : gc[r * 128 + t] + go[r * 128 + t];
        M[r][t] = (v - mu) * iv + 1e-4f;
    }
    __syncthreads();

    float y[64];
    for (int r = 0; r < 64; r++) {
        float acc = B1[t];
        for (int k = 0; k < 128; k++) acc += M[r][k] * W1[k * 128 + t];
        y[r] = fmaxf(acc, 0.f);
    }
    s = 0; s2 = 0;
    for (int r = 0; r < 64; r++) { s += y[r]; s2 += (double)y[r] * y[r]; }
    mud = s / 64.0;
    mu = (float)mud;
    iv = (float)rsqrt(s2 / 64.0 - mud * mud + 1e-5);
    __syncthreads();
    for (int r = 0; r < 64; r++) M[r][t] = (y[r] - mu) * iv + 1e-4f;
    __syncthreads();

    if (t < 10) {
        for (int r = 0; r < 64; r++) {
            float acc = B2[t];
            for (int k = 0; k < 128; k++) acc += M[r][k] * W2[k * 10 + t];
            Z[r][t] = acc;
        }
    }
    __syncthreads();
    if (t < 64) {
        float mx = -1e30f;
        for (int c = 0; c < 10; c++) mx = fmaxf(mx, Z[t][c]);
        float sm = 0;
        for (int c = 0; c < 10; c++) sm += expf(Z[t][c] - mx);
        float l = mx + logf(sm);
        for (int c = 0; c < 10; c++) out[which * 640 + t * 10 + c] = Z[t][c] - l;
    }
}

// -------- buffer set + layer driver --------
struct LBuf {
    float *log, *ssrc, *sdst, *asum, *agghs, *agge, *hm, *a2, *c2, *b1m;
    uint32_t* img;
};

static void run_layer_h(const LBuf& b, float* H, double* ds, int* I, cudaStream_t st,
                        cudaStream_t side, cudaEvent_t evFork, cudaEvent_t evJoin,
                        cudaEvent_t waitJ, int do_colstat, double* osums_next,
                        const float* xin, const float* ef, int fe,
                        const float* Wn, const float* We, const float* bb, const float* aa,
                        const int* row, const int* col,
                        float* xout, float* eout,
                        const float* attn, const float* attnp, int oneminus,
                        const float* mu, const float* inv, float* eattn, float* attnp_out,
                        int emit_csr, const int* cnt) {
    int* OFFS = I + 10000;
    int* FILL = I + 20001;
    int* PERM = I + 30001;
    int* IP   = I + 190001;
    int* ROWP = I + 350001;

    if (do_colstat) k_colstat<<<512, 128, 0, st>>>(xin, NN, ds);
    k_bprepW<<<96, 256, 0, st>>>(Wn, b.img + IM_WNH, b.img + IM_WNL);
    k_gemm<<<dim3(3, (NN + 127) / 128), 256, 0, st>>>(xin, b.img + IM_WNH, b.img + IM_WNL,
                                                      H, NN, 384, 128, 0,
                                                      bb, nullptr, nullptr, nullptr, nullptr,
                                                      ds, NN, nullptr);
    if (emit_csr) {
        double* DG; cudaGetSymbolAddress((void**)&DG, g_d);
        k_scan<<<1, 1024, 0, st>>>(cnt, OFFS, FILL, DG);
        k_fill<<<(NE + 255) / 256, 256, 0, st>>>(col, row, FILL, PERM, IP, ROWP);
    }
    if (waitJ) cudaStreamWaitEvent(st, waitJ, 0);
    k_wprep<<<192, 256, 0, st>>>(We, bb + 384, aa + 768, fe, eout ? 1 : 0,
                                 b.a2, b.c2, b.b1m,
                                 b.img + IM_WPH, b.img + IM_WPL, b.img + IM_WEH, b.img + IM_WEL);
    k_nodescore<<<(NN + 7) / 8, 256, 0, st>>>(H, aa, b.ssrc, b.sdst, b.hm);
    if (eout) {
        cudaEventRecord(evFork, st);
        cudaStreamWaitEvent(side, evFork, 0);
        k_gemm<<<dim3(1, (NE + 127) / 128), 256, 0, side>>>(ef, b.img + IM_WEH, b.img + IM_WEL,
                                                            eout, NE, 128, fe, 2,
                                                            b.b1m, b.hm, nullptr, row, col,
                                                            nullptr, 0, nullptr);
        cudaEventRecord(evJoin, side);
    }
    k_edgelogit<<<NE / 8, 256, 0, st>>>(ef, fe, row, col, IP, b.ssrc, b.sdst,
                                        b.a2, b.c2, attn, oneminus, mu, inv,
                                        b.log, eattn, attnp_out, eattn ? 1 : 0);
    k_nodeagg<<<NN, 128, 0, st>>>(OFFS, PERM, ROWP, b.log, H, ef, fe,
                                  attnp, oneminus, mu, inv,
                                  b.agghs, b.agge, b.asum);
    k_gemm<<<dim3(1, (NN + 127) / 128), 256, 0, st>>>(b.agge, b.img + IM_WPH, b.img + IM_WPL,
                                                      xout, NN, 128, 3 * fe, 1,
                                                      b.agghs, b.asum, bb + 384,
                                                      nullptr, nullptr, nullptr, 0, osums_next);
}

struct SideStream {
    cudaStream_t s;
    cudaEvent_t evF, evJ;
    cudaEvent_t fork[6], join[6];
    SideStream() {
        cudaStreamCreateWithFlags(&s, cudaStreamNonBlocking);
        cudaEventCreateWithFlags(&evF, cudaEventDisableTiming);
        cudaEventCreateWithFlags(&evJ, cudaEventDisableTiming);
        for (int i = 0; i < 6; i++) {
            cudaEventCreateWithFlags(&fork[i], cudaEventDisableTiming);
            cudaEventCreateWithFlags(&join[i], cudaEventDisableTiming);
        }
    }
};

extern "C" void kernel_launch(void* const* d_in, const int* in_sizes, int n_in,
                              void* d_out, int out_size) {
    static SideStream ss;
    float* F; cudaGetSymbolAddress((void**)&F, g_f);
    double* DS; cudaGetSymbolAddress((void**)&DS, g_d);
    int* I; cudaGetSymbolAddress((void**)&I, g_i);

    const float* x     = (const float*)d_in[0];
    const float* eattr = (const float*)d_in[1];
    const float* Wn0   = (const float*)d_in[2];
    const float* We0   = (const float*)d_in[3];
    const float* b0    = (const float*)d_in[4];
    const float* a0    = (const float*)d_in[5];
    const float* Wn    = (const float*)d_in[6];
    const float* We    = (const float*)d_in[7];
    const float* bb    = (const float*)d_in[8];
    const float* aa    = (const float*)d_in[9];
    const float* nattW = (const float*)d_in[10];
    const float* nattB = (const float*)d_in[11];
    const float* fcW1  = (const float*)d_in[12];
    const float* fcb1  = (const float*)d_in[13];
    const float* fcW2  = (const float*)d_in[14];
    const float* fcb2  = (const float*)d_in[15];
    const int* eidx    = (const int*)d_in[16];
    const int* batch   = (const int*)d_in[17];
    const int* row = eidx;
    const int* col = eidx + NE;
    int* CNT = I;

    LBuf bA = { F + O_LOG, F + O_SSRC, F + O_SDST, F + O_ASUM, F + O_AGGHS,
                F + O_AGGE, F + O_HM, F + O_A2, F + O_C2, F + O_B1M,
                (uint32_t*)(F + O_IMG) };
    LBuf bB = { F + O2_LOG, F + O2_SSRC, F + O2_SDST, F + O2_ASUM, F + O2_AGGHS,
                F + O2_AGGE, F + O2_HM, F + O2_A2, F + O2_C2, F + O2_B1M,
                (uint32_t*)(F + O2_IMG) };

    cudaMemsetAsync(CNT, 0, NN * sizeof(int), 0);
    k_count<<<(NE + 255) / 256, 256>>>(col, CNT, DS);

    run_layer_h(bA, F + O_H, DS + 0 * 256, I, 0, ss.s, ss.fork[0], ss.join[0], nullptr,
                1, DS + 1 * 256,
                x, eattr, 16, Wn0, We0, b0, a0, row, col,
                F + O_X1, F + O_EA, nullptr, nullptr, 0, nullptr, nullptr, nullptr, nullptr, 1, CNT);
    run_layer_h(bA, F + O_H, DS + 1 * 256, I, 0, ss.s, ss.fork[1], ss.join[1], ss.join[0],
                0, DS + 2 * 256,
                F + O_X1, F + O_EA, 128, Wn, We, bb, aa, row, col,
                F + O_X1, F + O_EB, nullptr, nullptr, 0, nullptr, nullptr, nullptr, nullptr, 0, nullptr);
    run_layer_h(bA, F + O_H, DS + 2 * 256, I, 0, ss.s, ss.fork[2], ss.join[2], ss.join[1],
                0, DS + 3 * 256,
                F + O_X1, F + O_EB, 128, Wn + 49152, We + 49152, bb + 768, aa + 1152, row, col,
                F + O_X1, F + O_EA, nullptr, nullptr, 0, nullptr, nullptr, nullptr, nullptr, 0, nullptr);
    run_layer_h(bA, F + O_H, DS + 3 * 256, I, 0, ss.s, ss.fork[3], ss.join[3], ss.join[2],
                0, nullptr,
                F + O_X1, F + O_EA, 128, Wn + 2 * 49152, We + 2 * 49152,
                bb + 2 * 768, aa + 2 * 1152, row, col,
                F + O_X1, F + O_EB, nullptr, nullptr, 0, nullptr, nullptr,
                F + O_EATTN, F + O_ATTNP, 0, nullptr);

    k_natt<<<(NN + 7) / 8, 256>>>(F + O_X1, nattW, nattB, F + O_XC, F + O_XO,
                                  DS + 4 * 256, DS + 5 * 256);
    cudaStreamWaitEvent(0, ss.join[3], 0);  // EB complete before edgemom/branches
    k_edgemom<<<1024, 128>>>(F + O_EB, F + O_EATTN, DS + DS_EDGEMOM);
    k_edgemomfin<<<1, 128>>>(DS + DS_EDGEMOM, F + O_MUC, F + O_INVC, F + O_MUO, F + O_INVO);
    cudaMemsetAsync(F + O_GC, 0, 2 * NG * 128 * sizeof(float), 0);

    // fork: branch B (XO) on side stream, branch A (XC) on stream 0
    cudaEventRecord(ss.evF, 0);
    cudaStreamWaitEvent(ss.s, ss.evF, 0);

    run_layer_h(bB, F + O2_H, DS + 5 * 256, I, ss.s, ss.s, ss.fork[5], ss.join[5], nullptr,
                0, nullptr,
                F + O_XO, F + O_EB, 128, Wn + 4 * 49152, We + 4 * 49152,
                bb + 4 * 768, aa + 4 * 1152, row, col,
                F + O_XO, nullptr, F + O_EATTN, F + O_ATTNP, 1,
                F + O_MUO, F + O_INVO, nullptr, nullptr, 0, nullptr);
    k_segsum<<<(NN * 128 + 255) / 256, 256, 0, ss.s>>>(F + O_XO, batch, F + O_GO);
    cudaEventRecord(ss.evJ, ss.s);

    run_layer_h(bA, F + O_H, DS + 4 * 256, I, 0, 0, ss.fork[4], ss.join[4], nullptr,
                0, nullptr,
                F + O_XC, F + O_EB, 128, Wn + 3 * 49152, We + 3 * 49152,
                bb + 3 * 768, aa + 3 * 1152, row, col,
                F + O_XC, nullptr, F + O_EATTN, F + O_ATTNP, 0,
                F + O_MUC, F + O_INVC, nullptr, nullptr, 0, nullptr);
    k_segsum<<<(NN * 128 + 255) / 256, 256>>>(F + O_XC, batch, F + O_GC);

    cudaStreamWaitEvent(0, ss.evJ, 0);
    k_readout<<<3, 128>>>(F + O_GC, F + O_GO, fcW1, fcb1, fcW2, fcb2, (float*)d_out);
}

// round 16
// speedup vs baseline: 1.0603x; 1.0603x over previous
#include <cuda_runtime.h>
#include <cuda_bf16.h>
#include <math.h>
#include <stdint.h>

#define NN 10000
#define NE 160000
#define NG 64

__device__ __align__(128) float g_f[68450000];
__device__ double g_d[2048];
__device__ int    g_i[520064];

#define O_EA    0UL
#define O_EB    20480000UL
#define O_H     40960000UL
#define O_X1    44800000UL
#define O_ATTNP 46080000UL
#define O_XC    47360000UL
#define O_XO    48640000UL
#define O_AGGE  49920000UL
#define O_AGGHS 53760000UL
#define O_HM    55040000UL
#define O_LOG   56320000UL
#define O_EATTN 56800000UL
#define O_SSRC  56960000UL
#define O_SDST  56990000UL
#define O_ASUM  57020000UL
#define O_A2    57099152UL
#define O_C2    57099556UL
#define O_B1M   57115924UL
#define O_MUC   57116308UL
#define O_INVC  57116436UL
#define O_MUO   57116564UL
#define O_INVO  57116692UL
#define O_GC    57116820UL
#define O_GO    57125012UL
#define O_IMG   57140000UL
#define O2_LOG   57400000UL
#define O2_SSRC  57880000UL
#define O2_SDST  57910000UL
#define O2_ASUM  57940000UL
#define O2_AGGHS 57970000UL
#define O2_AGGE  59250000UL
#define O2_HM    63090000UL
#define O2_A2    64370000UL
#define O2_C2    64370404UL
#define O2_B1M   64370410UL
#define O2_IMG   64370560UL
#define O2_H     64600000UL
#define DS_EDGEMOM 1536

#define IM_WNH 0
#define IM_WNL 49152
#define IM_WPH 98304
#define IM_WPL 147456
#define IM_WEH 196608
#define IM_WEL 212992

__device__ __forceinline__ uint32_t packsplit(float x, float y, uint32_t& lo) {
    __nv_bfloat162 h = __floats2bfloat162_rn(x, y);
    __nv_bfloat162 l = __floats2bfloat162_rn(x - __low2float(h), y - __high2float(h));
    lo = *(uint32_t*)&l;
    return *(uint32_t*)&h;
}

// -------- CSR --------
__global__ void k_count(const int* __restrict__ col, int* __restrict__ cnt,
                        double* __restrict__ ds) {
    int i = blockIdx.x * blockDim.x + threadIdx.x;
    if (blockIdx.x == 0 && threadIdx.x < 256) ds[threadIdx.x] = 0.0;
    if (i < NE) atomicAdd(&cnt[col[i]], 1);
}
__global__ void k_scan(const int* __restrict__ cnt, int* __restrict__ offs,
                       int* __restrict__ fill, double* __restrict__ ds) {
    __shared__ int sm[1024];
    int t = threadIdx.x;
    ds[256 + t] = 0.0;
    if (t < 768) ds[1280 + t] = 0.0;
    const int per = (NN + 1023) / 1024;
    int b = t * per, e = min(NN, b + per);
    int s = 0;
    for (int i = b; i < e; i++) s += cnt[i];
    sm[t] = s; __syncthreads();
    for (int o = 1; o < 1024; o <<= 1) {
        int v = (t >= o) ? sm[t - o] : 0;
        __syncthreads(); sm[t] += v; __syncthreads();
    }
    int base = (t == 0) ? 0 : sm[t - 1];
    for (int i = b; i < e; i++) { offs[i] = base; fill[i] = base; base += cnt[i]; }
    if (t == 1023) offs[NN] = sm[1023];
}
__global__ void k_fill(const int* __restrict__ col, const int* __restrict__ row,
                       int* __restrict__ fill, int* __restrict__ perm,
                       int* __restrict__ ip, int* __restrict__ rowp) {
    int i = blockIdx.x * blockDim.x + threadIdx.x;
    if (i < NE) {
        int p = atomicAdd(&fill[col[i]], 1);
        perm[p] = i; ip[i] = p; rowp[p] = row[i];
    }
}

// -------- BN stats --------
__global__ void k_colstat(const float* __restrict__ X, int rows, double* __restrict__ sums) {
    int c = threadIdx.x;
    double s = 0, s2 = 0;
    for (int r = blockIdx.x * 8; r < rows; r += gridDim.x * 8) {
        #pragma unroll
        for (int q = 0; q < 8; q++) {
            int rr = r + q;
            float v = (rr < rows) ? X[(size_t)rr * 128 + c] : 0.f;
            s += v; s2 += (double)v * v;
        }
    }
    atomicAdd(&sums[c], s);
    atomicAdd(&sums[128 + c], s2);
}
__global__ void k_edgemom(const float* __restrict__ E4, const float* __restrict__ attn,
                          double* __restrict__ sums) {
    int t = threadIdx.x;
    double sc = 0, sc2 = 0, so = 0, so2 = 0;
    #pragma unroll 4
    for (int r = blockIdx.x; r < NE; r += gridDim.x) {
        float w = attn[r];
        float v = E4[(size_t)r * 128 + t];
        float tc = w * v, to = (1.f - w) * v;
        sc += tc; sc2 += (double)tc * tc;
        so += to; so2 += (double)to * to;
    }
    atomicAdd(&sums[t], sc); atomicAdd(&sums[128 + t], sc2);
    atomicAdd(&sums[256 + t], so); atomicAdd(&sums[384 + t], so2);
}
__global__ void k_edgemomfin(const double* __restrict__ sums, float* __restrict__ muc,
                             float* __restrict__ invc, float* __restrict__ muo,
                             float* __restrict__ invo) {
    int c = threadIdx.x;
    double m = sums[c] / NE, v = sums[128 + c] / NE - m * m;
    muc[c] = (float)m; invc[c] = (float)rsqrt(v + 1e-5);
    m = sums[256 + c] / NE; v = sums[384 + c] / NE - m * m;
    muo[c] = (float)m; invo[c] = (float)rsqrt(v + 1e-5);
}

// -------- B image prep --------
__global__ void k_bprepW(const float* __restrict__ Wn, uint32_t* __restrict__ bh,
                         uint32_t* __restrict__ bl) {
    int i = blockIdx.x * blockDim.x + threadIdx.x;
    if (i >= 64 * 384) return;
    int k2 = i / 384, n = i % 384;
    float v0 = Wn[(size_t)(2 * k2) * 384 + n];
    float v1 = Wn[(size_t)(2 * k2 + 1) * 384 + n];
    uint32_t lo; uint32_t hi = packsplit(v0, v1, lo);
    bh[i] = hi; bl[i] = lo;
}

__global__ void k_wprep(const float* __restrict__ We, const float* __restrict__ b1,
                        const float* __restrict__ a2, int fe, int need_em,
                        float* __restrict__ A2, float* __restrict__ C2,
                        float* __restrict__ B1M, uint32_t* __restrict__ wph,
                        uint32_t* __restrict__ wpl, uint32_t* __restrict__ weh,
                        uint32_t* __restrict__ wel) {
    int i = blockIdx.x * blockDim.x + threadIdx.x;
    if (i < fe * 3) {
        int f = i / 3, h = i % 3;
        float s = 0;
        for (int d = 0; d < 128; d++) s += We[(size_t)(f * 3 + h) * 128 + d] * a2[h * 128 + d];
        A2[i] = s;
    }
    if (i < 3) {
        float s = 0;
        for (int d = 0; d < 128; d++) s += b1[i * 128 + d] * a2[i * 128 + d];
        C2[i] = s;
    }
    if (i < 128) B1M[i] = (b1[i] + b1[128 + i] + b1[256 + i]) * (1.f / 3.f);
    int tot = (3 * fe / 2) * 128;
    if (i < tot) {
        int k2 = i / 128, d = i % 128;
        int ka = 2 * k2, kb = 2 * k2 + 1;
        float v0 = We[(size_t)((ka % fe) * 3 + (ka / fe)) * 128 + d];
        float v1 = We[(size_t)((kb % fe) * 3 + (kb / fe)) * 128 + d];
        uint32_t lo; uint32_t hi = packsplit(v0, v1, lo);
        wph[i] = hi; wpl[i] = lo;
    }
    if (need_em && i < (fe / 2) * 128) {
        int k2 = i / 128, d = i % 128;
        float v0 = (We[(size_t)(2 * k2 * 3) * 128 + d] + We[(size_t)(2 * k2 * 3 + 1) * 128 + d] +
                    We[(size_t)(2 * k2 * 3 + 2) * 128 + d]) * (1.f / 3.f);
        float v1 = (We[(size_t)((2 * k2 + 1) * 3) * 128 + d] + We[(size_t)((2 * k2 + 1) * 3 + 1) * 128 + d] +
                    We[(size_t)((2 * k2 + 1) * 3 + 2) * 128 + d]) * (1.f / 3.f);
        uint32_t lo; uint32_t hi = packsplit(v0, v1, lo);
        weh[i] = hi; wel[i] = lo;
    }
}

// -------- node scores --------
__global__ void k_nodescore(const float* __restrict__ H, const float* __restrict__ a,
                            float* __restrict__ ssrc, float* __restrict__ sdst,
                            float* __restrict__ hm) {
    int n = blockIdx.x * (blockDim.x >> 5) + (threadIdx.x >> 5);
    int lane = threadIdx.x & 31;
    if (n >= NN) return;
    const float* hp = H + (size_t)n * 384;
    float s[6] = {0, 0, 0, 0, 0, 0};
    #pragma unroll
    for (int q = 0; q < 4; q++) {
        int f = lane + q * 32;
        float h0 = hp[f], h1 = hp[128 + f], h2 = hp[256 + f];
        hm[(size_t)n * 128 + f] = (h0 + h1 + h2) * (1.f / 3.f);
        s[0] += h0 * a[f];       s[1] += h1 * a[128 + f]; s[2] += h2 * a[256 + f];
        s[3] += h0 * a[384 + f]; s[4] += h1 * a[512 + f]; s[5] += h2 * a[640 + f];
    }
    #pragma unroll
    for (int o = 16; o > 0; o >>= 1)
        #pragma unroll
        for (int q = 0; q < 6; q++) s[q] += __shfl_xor_sync(0xffffffffu, s[q], o);
    if (lane < 3) {
        ssrc[n * 3 + lane] = s[lane];
        sdst[n * 3 + lane] = s[3 + lane];
    }
}

// -------- edge logits --------
__global__ void k_edgelogit(const float* __restrict__ ef, int fe,
                            const int* __restrict__ row, const int* __restrict__ colv,
                            const int* __restrict__ ip,
                            const float* __restrict__ ssrc, const float* __restrict__ sdst,
                            const float* __restrict__ A2, const float* __restrict__ C2,
                            const float* __restrict__ attn, int oneminus,
                            const float* __restrict__ mu, const float* __restrict__ inv,
                            float* __restrict__ logits, float* __restrict__ eattn,
                            float* __restrict__ attnp, int do_attn) {
    int gw = (blockIdx.x * blockDim.x + threadIdx.x) >> 5;
    int lane = threadIdx.x & 31;
    if (gw >= NE) return;
    float w = 1.f;
    if (attn) { w = attn[gw]; if (oneminus) w = 1.f - w; }
    float p0 = 0, p1 = 0, p2 = 0;
    if (fe == 128) {
        int i = lane * 4;
        float4 v4 = *(const float4*)&ef[(size_t)gw * 128 + i];
        float v[4] = {v4.x, v4.y, v4.z, v4.w};
        #pragma unroll
        for (int q = 0; q < 4; q++) {
            float v1 = v[q];
            if (mu) v1 = (w * v1 - mu[i + q]) * inv[i + q] + 1e-4f;
            p0 += v1 * A2[(i + q) * 3 + 0];
            p1 += v1 * A2[(i + q) * 3 + 1];
            p2 += v1 * A2[(i + q) * 3 + 2];
        }
    } else {
        for (int i = lane; i < fe; i += 32) {
            float v = ef[(size_t)gw * fe + i];
            if (mu) v = (w * v - mu[i]) * inv[i] + 1e-4f;
            p0 += v * A2[i * 3 + 0]; p1 += v * A2[i * 3 + 1]; p2 += v * A2[i * 3 + 2];
        }
    }
    #pragma unroll
    for (int o = 16; o > 0; o >>= 1) {
        p0 += __shfl_down_sync(0xffffffffu, p0, o);
        p1 += __shfl_down_sync(0xffffffffu, p1, o);
        p2 += __shfl_down_sync(0xffffffffu, p2, o);
    }
    if (lane == 0) {
        int r = row[gw], c = colv[gw];
        float l0 = ssrc[r * 3 + 0] + sdst[c * 3 + 0] + p0 + C2[0];
        float l1 = ssrc[r * 3 + 1] + sdst[c * 3 + 1] + p1 + C2[1];
        float l2 = ssrc[r * 3 + 2] + sdst[c * 3 + 2] + p2 + C2[2];
        l0 = l0 > 0.f ? l0 : 0.2f * l0;
        l1 = l1 > 0.f ? l1 : 0.2f * l1;
        l2 = l2 > 0.f ? l2 : 0.2f * l2;
        int pos = ip[gw];
        logits[pos * 3 + 0] = l0; logits[pos * 3 + 1] = l1; logits[pos * 3 + 2] = l2;
        if (do_attn) {
            float m = (l0 + l1 + l2) * (1.f / 3.f);
            float at = 1.f / (1.f + expf(-m));
            eattn[gw] = at;
            attnp[pos] = at;
        }
    }
}

// -------- per-node softmax + aggregation --------
__global__ void k_nodeagg(const int* __restrict__ offs, const int* __restrict__ perm,
                          const int* __restrict__ rowp, float* __restrict__ L,
                          const float* __restrict__ H, const float* __restrict__ ef, int fe,
                          const float* __restrict__ attnp, int oneminus,
                          const float* __restrict__ mu, const float* __restrict__ inv,
                          float* __restrict__ agghs, float* __restrict__ aggE,
                          float* __restrict__ asum) {
    __shared__ float red[3][128];
    __shared__ float sval[6];
    int n = blockIdx.x, t = threadIdx.x;
    int s = offs[n], e = offs[n + 1];

    float mx0 = -1e30f, mx1 = -1e30f, mx2 = -1e30f;
    for (int j = s + t; j < e; j += 128) {
        mx0 = fmaxf(mx0, L[j * 3 + 0]);
        mx1 = fmaxf(mx1, L[j * 3 + 1]);
        mx2 = fmaxf(mx2, L[j * 3 + 2]);
    }
    red[0][t] = mx0; red[1][t] = mx1; red[2][t] = mx2;
    __syncthreads();
    for (int o = 64; o > 0; o >>= 1) {
        if (t < o) {
            red[0][t] = fmaxf(red[0][t], red[0][t + o]);
            red[1][t] = fmaxf(red[1][t], red[1][t + o]);
            red[2][t] = fmaxf(red[2][t], red[2][t + o]);
        }
        __syncthreads();
    }
    if (t < 3) sval[t] = red[t][0];
    __syncthreads();
    float m0 = sval[0], m1 = sval[1], m2 = sval[2];

    float sm0 = 0, sm1 = 0, sm2 = 0;
    for (int j = s + t; j < e; j += 128) {
        float w0 = expf(L[j * 3 + 0] - m0);
        float w1 = expf(L[j * 3 + 1] - m1);
        float w2 = expf(L[j * 3 + 2] - m2);
        L[j * 3 + 0] = w0; L[j * 3 + 1] = w1; L[j * 3 + 2] = w2;
        sm0 += w0; sm1 += w1; sm2 += w2;
    }
    red[0][t] = sm0; red[1][t] = sm1; red[2][t] = sm2;
    __syncthreads();
    for (int o = 64; o > 0; o >>= 1) {
        if (t < o) {
            red[0][t] += red[0][t + o];
            red[1][t] += red[1][t + o];
            red[2][t] += red[2][t + o];
        }
        __syncthreads();
    }
    if (t < 3) sval[t] = 1.f / (red[t][0] + 1e-16f);
    if (t >= 3 && t < 6) sval[t] = red[t - 3][0];
    __syncthreads();
    float i0 = sval[0], i1 = sval[1], i2 = sval[2];
    if (t == 0) {
        asum[n * 3 + 0] = sval[3] * i0;
        asum[n * 3 + 1] = sval[4] * i1;
        asum[n * 3 + 2] = sval[5] * i2;
    }

    float a_hs = 0, aE0 = 0, aE1 = 0, aE2 = 0;
    for (int j0 = s; j0 < e; j0 += 4) {
        int cnt = e - j0; if (cnt > 4) cnt = 4;
        int r[4], id[4];
        float w0[4], w1[4], w2[4], ww[4];
        #pragma unroll
        for (int q = 0; q < 4; q++) {
            if (q < cnt) {
                r[q] = rowp[j0 + q];
                w0[q] = L[(j0 + q) * 3 + 0] * i0;
                w1[q] = L[(j0 + q) * 3 + 1] * i1;
                w2[q] = L[(j0 + q) * 3 + 2] * i2;
                id[q] = perm[j0 + q];
                if (mu) { ww[q] = attnp[j0 + q]; if (oneminus) ww[q] = 1.f - ww[q]; }
            }
        }
        #pragma unroll
        for (int q = 0; q < 4; q++) {
            if (q < cnt) {
                const float* hp = &H[(size_t)r[q] * 384];
                a_hs += w0[q] * hp[t] + w1[q] * hp[128 + t] + w2[q] * hp[256 + t];
                if (t < fe) {
                    float v = ef[(size_t)id[q] * fe + t];
                    if (mu) v = (ww[q] * v - mu[t]) * inv[t] + 1e-4f;
                    aE0 += w0[q] * v; aE1 += w1[q] * v; aE2 += w2[q] * v;
                }
            }
        }
    }
    agghs[(size_t)n * 128 + t] = a_hs;
    if (t < fe) {
        aggE[(size_t)n * 3 * fe + 0 * fe + t] = aE0;
        aggE[(size_t)n * 3 * fe + 1 * fe + t] = aE1;
        aggE[(size_t)n * 3 * fe + 2 * fe + t] = aE2;
    }
}

// -------- bf16-split tensor-core GEMM --------
__device__ __forceinline__ void mma_bf(float c[4], const uint32_t a[4], const uint32_t b[2]) {
    asm volatile(
        "mma.sync.aligned.m16n8k16.row.col.f32.bf16.bf16.f32 "
        "{%0,%1,%2,%3},{%4,%5,%6,%7},{%8,%9},{%0,%1,%2,%3};\n"
        : "+f"(c[0]), "+f"(c[1]), "+f"(c[2]), "+f"(c[3])
        : "r"(a[0]), "r"(a[1]), "r"(a[2]), "r"(a[3]), "r"(b[0]), "r"(b[1]));
}

__global__ void __launch_bounds__(256, 2)
k_gemm(const float* __restrict__ A, const uint32_t* __restrict__ bhg,
       const uint32_t* __restrict__ blg,
       float* __restrict__ C, int M, int N, int K, int mode,
       const float* __restrict__ p0, const float* __restrict__ p1,
       const float* __restrict__ p2,
       const int* __restrict__ ridx, const int* __restrict__ cidx,
       const double* __restrict__ dsums, int bnrows) {
    __shared__ uint32_t Ah[8][136], Al[8][136], Bh[8][136], Bl[8][136];
    __shared__ float bnmu[128], bninv[128];
    int tid = threadIdx.x, wid = tid >> 5, lane = tid & 31;
    int g = lane >> 2, tk = lane & 3;
    int bm = blockIdx.y * 128, bn = blockIdx.x * 128;
    int wm = (wid & 1) * 64, wn = (wid >> 1) * 32;

    if (dsums) {
        if (tid < 128) {
            double m = dsums[tid] / bnrows;
            double v = dsums[128 + tid] / bnrows - m * m;
            bnmu[tid] = (float)m;
            bninv[tid] = (float)rsqrt(v + 1e-5);
        }
        __syncthreads();
    }

    float acc[4][4][4];
    #pragma unroll
    for (int i = 0; i < 4; i++)
        #pragma unroll
        for (int j = 0; j < 4; j++)
            #pragma unroll
            for (int q = 0; q < 4; q++) acc[i][j][q] = 0.f;

    int bk2 = tid >> 5, bn4 = (tid & 31) * 4;

    for (int k0 = 0; k0 < K; k0 += 16) {
        #pragma unroll
        for (int rep = 0; rep < 2; rep++) {
            int idx = tid + rep * 256;
            int r = idx >> 2, kq = (idx & 3) * 4;
            float4 av = make_float4(0.f, 0.f, 0.f, 0.f);
            if (bm + r < M) {
                av = *(const float4*)&A[(size_t)(bm + r) * K + k0 + kq];
                if (dsums) {
                    int kk = k0 + kq;
                    av.x = (av.x - bnmu[kk + 0]) * bninv[kk + 0] + 1e-4f;
                    av.y = (av.y - bnmu[kk + 1]) * bninv[kk + 1] + 1e-4f;
                    av.z = (av.z - bnmu[kk + 2]) * bninv[kk + 2] + 1e-4f;
                    av.w = (av.w - bnmu[kk + 3]) * bninv[kk + 3] + 1e-4f;
                }
            }
            uint32_t lo;
            int k2 = kq >> 1;
            Ah[k2][r] = packsplit(av.x, av.y, lo); Al[k2][r] = lo;
            Ah[k2 + 1][r] = packsplit(av.z, av.w, lo); Al[k2 + 1][r] = lo;
        }
        {
            size_t gi = (size_t)((k0 >> 1) + bk2) * N + bn + bn4;
            uint4 hv = *(const uint4*)&bhg[gi];
            uint4 lv = *(const uint4*)&blg[gi];
            *(uint4*)&Bh[bk2][bn4] = hv;
            *(uint4*)&Bl[bk2][bn4] = lv;
        }
        __syncthreads();

        uint32_t bh[4][2], bl[4][2];
        #pragma unroll
        for (int nf = 0; nf < 4; nf++) {
            int nc = wn + nf * 8 + g;
            bh[nf][0] = Bh[tk][nc];     bh[nf][1] = Bh[tk + 4][nc];
            bl[nf][0] = Bl[tk][nc];     bl[nf][1] = Bl[tk + 4][nc];
        }
        #pragma unroll
        for (int mf = 0; mf < 4; mf++) {
            int mr = wm + mf * 16 + g;
            uint32_t ah[4], al[4];
            ah[0] = Ah[tk][mr];     ah[1] = Ah[tk][mr + 8];
            ah[2] = Ah[tk + 4][mr]; ah[3] = Ah[tk + 4][mr + 8];
            al[0] = Al[tk][mr];     al[1] = Al[tk][mr + 8];
            al[2] = Al[tk + 4][mr]; al[3] = Al[tk + 4][mr + 8];
            #pragma unroll
            for (int nf = 0; nf < 4; nf++) {
                mma_bf(acc[mf][nf], ah, bh[nf]);
                mma_bf(acc[mf][nf], ah, bl[nf]);
                mma_bf(acc[mf][nf], al, bh[nf]);
            }
        }
        __syncthreads();
    }

    #pragma unroll
    for (int mf = 0; mf < 4; mf++) {
        int r0 = bm + wm + mf * 16 + g;
        #pragma unroll
        for (int half = 0; half < 2; half++) {
            int m = half ? (r0 + 8) : r0;
            if (m >= M) continue;
            int rr = 0, cc = 0;
            if (mode == 2) { rr = ridx[m]; cc = cidx[m]; }
            #pragma unroll
            for (int nf = 0; nf < 4; nf++) {
                int n0 = bn + wn + nf * 8 + tk * 2;
                float v0 = acc[mf][nf][half * 2 + 0];
                float v1 = acc[mf][nf][half * 2 + 1];
                if (mode == 0) {
                    v0 += p0[n0]; v1 += p0[n0 + 1];
                } else if (mode == 1) {
                    float s0 = p1[m * 3 + 0], s1 = p1[m * 3 + 1], s2 = p1[m * 3 + 2];
                    v0 += p0[(size_t)m * 128 + n0];
                    v0 += s0 * p2[n0] + s1 * p2[128 + n0] + s2 * p2[256 + n0];
                    v0 = fmaxf(v0 * (1.f / 3.f), 0.f);
                    v1 += p0[(size_t)m * 128 + n0 + 1];
                    v1 += s0 * p2[n0 + 1] + s1 * p2[128 + n0 + 1] + s2 * p2[256 + n0 + 1];
                    v1 = fmaxf(v1 * (1.f / 3.f), 0.f);
                } else {
                    v0 += p0[n0] + p1[(size_t)rr * 128 + n0] + p1[(size_t)cc * 128 + n0];
                    v0 = fmaxf(v0, 0.f);
                    v1 += p0[n0 + 1] + p1[(size_t)rr * 128 + n0 + 1] + p1[(size_t)cc * 128 + n0 + 1];
                    v1 = fmaxf(v1, 0.f);
                }
                *(float2*)&C[(size_t)m * N + n0] = make_float2(v0, v1);
            }
        }
    }
}

// -------- node attention split --------
__global__ void k_natt(const float* __restrict__ x, const float* __restrict__ W,
                       const float* __restrict__ b, float* __restrict__ xc,
                       float* __restrict__ xo) {
    int n = blockIdx.x * (blockDim.x >> 5) + (threadIdx.x >> 5);
    int lane = threadIdx.x & 31;
    if (n >= NN) return;
    float d0 = 0, d1 = 0;
    for (int i = lane; i < 128; i += 32) {
        float v = x[(size_t)n * 128 + i];
        d0 += v * W[i * 2 + 0]; d1 += v * W[i * 2 + 1];
    }
    #pragma unroll
    for (int o = 16; o > 0; o >>= 1) {
        d0 += __shfl_xor_sync(0xffffffffu, d0, o);
        d1 += __shfl_xor_sync(0xffffffffu, d1, o);
    }
    d0 += b[0]; d1 += b[1];
    float mx = fmaxf(d0, d1);
    float e0 = expf(d0 - mx), e1 = expf(d1 - mx);
    float inv = 1.f / (e0 + e1);
    float n0 = e0 * inv, n1 = e1 * inv;
    for (int i = lane; i < 128; i += 32) {
        float v = x[(size_t)n * 128 + i];
        xc[(size_t)n * 128 + i] = n0 * v;
        xo[(size_t)n * 128 + i] = n1 * v;
    }
}

__global__ void k_segsum(const float* __restrict__ x, const int* __restrict__ batch,
                         float* __restrict__ g) {
    int i = blockIdx.x * blockDim.x + threadIdx.x;
    if (i < NN * 128) {
        int n = i >> 7;
        atomicAdd(&g[(size_t)batch[n] * 128 + (i & 127)], x[i]);
    }
}

__global__ void k_readout(const float* __restrict__ gc, const float* __restrict__ go,
                          const float* __restrict__ W1s, const float* __restrict__ b1s,
                          const float* __restrict__ W2s, const float* __restrict__ b2s,
                          float* __restrict__ out) {
    int which = blockIdx.x, t = threadIdx.x;
    __shared__ float M[64][129];
    __shared__ float Z[64][12];
    const float* W1 = W1s + which * 16384;
    const float* B1 = b1s + which * 128;
    const float* W2 = W2s + which * 1280;
    const float* B2 = b2s + which * 10;

    double s = 0, s2 = 0;
    for (int r = 0; r < 64; r++) {
        float v = (which == 0) ? gc[r * 128 + t]
                : (which == 1) ? go[r * 128 + t]
                               : gc[r * 128 + t] + go[r * 128 + t];
        s += v; s2 += (double)v * v;
    }
    double mud = s / 64.0;
    float mu = (float)mud;
    float iv = (float)rsqrt(s2 / 64.0 - mud * mud + 1e-5);
    for (int r = 0; r < 64; r++) {
        float v = (which == 0) ? gc[r * 128 + t]
                : (which == 1) ? go[r * 128 + t]
                               : gc[r * 128 + t] + go[r * 128 + t];
        M[r][t] = (v - mu) * iv + 1e-4f;
    }
    __syncthreads();

    float y[64];
    for (int r = 0; r < 64; r++) {
        float acc = B1[t];
        for (int k = 0; k < 128; k++) acc += M[r][k] * W1[k * 128 + t];
        y[r] = fmaxf(acc, 0.f);
    }
    s = 0; s2 = 0;
    for (int r = 0; r < 64; r++) { s += y[r]; s2 += (double)y[r] * y[r]; }
    mud = s / 64.0;
    mu = (float)mud;
    iv = (float)rsqrt(s2 / 64.0 - mud * mud + 1e-5);
    __syncthreads();
    for (int r = 0; r < 64; r++) M[r][t] = (y[r] - mu) * iv + 1e-4f;
    __syncthreads();

    if (t < 10) {
        for (int r = 0; r < 64; r++) {
            float acc = B2[t];
            for (int k = 0; k < 128; k++) acc += M[r][k] * W2[k * 10 + t];
            Z[r][t] = acc;
        }
    }
    __syncthreads();
    if (t < 64) {
        float mx = -1e30f;
        for (int c = 0; c < 10; c++) mx = fmaxf(mx, Z[t][c]);
        float sm = 0;
        for (int c = 0; c < 10; c++) sm += expf(Z[t][c] - mx);
        float l = mx + logf(sm);
        for (int c = 0; c < 10; c++) out[which * 640 + t * 10 + c] = Z[t][c] - l;
    }
}

// -------- buffer set + layer driver --------
struct LBuf {
    float *log, *ssrc, *sdst, *asum, *agghs, *agge, *hm, *a2, *c2, *b1m;
    uint32_t* img;
};

static void run_layer_h(const LBuf& b, float* H, double* ds, int* I, cudaStream_t st,
                        cudaStream_t side, cudaEvent_t evFork, cudaEvent_t evJoin,
                        cudaEvent_t waitJ,
                        const float* xin, const float* ef, int fe,
                        const float* Wn, const float* We, const float* bb, const float* aa,
                        const int* row, const int* col,
                        float* xout, float* eout,
                        const float* attn, const float* attnp, int oneminus,
                        const float* mu, const float* inv, float* eattn, float* attnp_out,
                        int emit_csr, const int* cnt) {
    int* OFFS = I + 10000;
    int* FILL = I + 20001;
    int* PERM = I + 30001;
    int* IP   = I + 190001;
    int* ROWP = I + 350001;

    k_colstat<<<512, 128, 0, st>>>(xin, NN, ds);
    k_bprepW<<<96, 256, 0, st>>>(Wn, b.img + IM_WNH, b.img + IM_WNL);
    k_gemm<<<dim3(3, (NN + 127) / 128), 256, 0, st>>>(xin, b.img + IM_WNH, b.img + IM_WNL,
                                                      H, NN, 384, 128, 0,
                                                      bb, nullptr, nullptr, nullptr, nullptr,
                                                      ds, NN);
    if (emit_csr) {
        double* DG; cudaGetSymbolAddress((void**)&DG, g_d);
        k_scan<<<1, 1024, 0, st>>>(cnt, OFFS, FILL, DG);
        k_fill<<<(NE + 255) / 256, 256, 0, st>>>(col, row, FILL, PERM, IP, ROWP);
    }
    if (waitJ) cudaStreamWaitEvent(st, waitJ, 0);
    k_wprep<<<192, 256, 0, st>>>(We, bb + 384, aa + 768, fe, eout ? 1 : 0,
                                 b.a2, b.c2, b.b1m,
                                 b.img + IM_WPH, b.img + IM_WPL, b.img + IM_WEH, b.img + IM_WEL);
    k_nodescore<<<(NN + 7) / 8, 256, 0, st>>>(H, aa, b.ssrc, b.sdst, b.hm);
    if (eout) {
        cudaEventRecord(evFork, st);
        cudaStreamWaitEvent(side, evFork, 0);
        k_gemm<<<dim3(1, (NE + 127) / 128), 256, 0, side>>>(ef, b.img + IM_WEH, b.img + IM_WEL,
                                                            eout, NE, 128, fe, 2,
                                                            b.b1m, b.hm, nullptr, row, col,
                                                            nullptr, 0);
        cudaEventRecord(evJoin, side);
    }
    k_edgelogit<<<NE / 8, 256, 0, st>>>(ef, fe, row, col, IP, b.ssrc, b.sdst,
                                        b.a2, b.c2, attn, oneminus, mu, inv,
                                        b.log, eattn, attnp_out, eattn ? 1 : 0);
    k_nodeagg<<<NN, 128, 0, st>>>(OFFS, PERM, ROWP, b.log, H, ef, fe,
                                  attnp, oneminus, mu, inv,
                                  b.agghs, b.agge, b.asum);
    k_gemm<<<dim3(1, (NN + 127) / 128), 256, 0, st>>>(b.agge, b.img + IM_WPH, b.img + IM_WPL,
                                                      xout, NN, 128, 3 * fe, 1,
                                                      b.agghs, b.asum, bb + 384,
                                                      nullptr, nullptr, nullptr, 0);
}

struct SideStream {
    cudaStream_t s;
    cudaEvent_t evF, evJ, evEL, evMom;
    cudaEvent_t fork[6], join[6];
    SideStream() {
        cudaStreamCreateWithFlags(&s, cudaStreamNonBlocking);
        cudaEventCreateWithFlags(&evF, cudaEventDisableTiming);
        cudaEventCreateWithFlags(&evJ, cudaEventDisableTiming);
        cudaEventCreateWithFlags(&evEL, cudaEventDisableTiming);
        cudaEventCreateWithFlags(&evMom, cudaEventDisableTiming);
        for (int i = 0; i < 6; i++) {
            cudaEventCreateWithFlags(&fork[i], cudaEventDisableTiming);
            cudaEventCreateWithFlags(&join[i], cudaEventDisableTiming);
        }
    }
};

extern "C" void kernel_launch(void* const* d_in, const int* in_sizes, int n_in,
                              void* d_out, int out_size) {
    static SideStream ss;
    float* F; cudaGetSymbolAddress((void**)&F, g_f);
    double* DS; cudaGetSymbolAddress((void**)&DS, g_d);
    int* I; cudaGetSymbolAddress((void**)&I, g_i);

    const float* x     = (const float*)d_in[0];
    const float* eattr = (const float*)d_in[1];
    const float* Wn0   = (const float*)d_in[2];
    const float* We0   = (const float*)d_in[3];
    const float* b0    = (const float*)d_in[4];
    const float* a0    = (const float*)d_in[5];
    const float* Wn    = (const float*)d_in[6];
    const float* We    = (const float*)d_in[7];
    const float* bb    = (const float*)d_in[8];
    const float* aa    = (const float*)d_in[9];
    const float* nattW = (const float*)d_in[10];
    const float* nattB = (const float*)d_in[11];
    const float* fcW1  = (const float*)d_in[12];
    const float* fcb1  = (const float*)d_in[13];
    const float* fcW2  = (const float*)d_in[14];
    const float* fcb2  = (const float*)d_in[15];
    const int* eidx    = (const int*)d_in[16];
    const int* batch   = (const int*)d_in[17];
    const int* row = eidx;
    const int* col = eidx + NE;
    int* CNT = I;

    LBuf bA = { F + O_LOG, F + O_SSRC, F + O_SDST, F + O_ASUM, F + O_AGGHS,
                F + O_AGGE, F + O_HM, F + O_A2, F + O_C2, F + O_B1M,
                (uint32_t*)(F + O_IMG) };
    LBuf bB = { F + O2_LOG, F + O2_SSRC, F + O2_SDST, F + O2_ASUM, F + O2_AGGHS,
                F + O2_AGGE, F + O2_HM, F + O2_A2, F + O2_C2, F + O2_B1M,
                (uint32_t*)(F + O2_IMG) };

    cudaMemsetAsync(CNT, 0, NN * sizeof(int), 0);
    k_count<<<(NE + 255) / 256, 256>>>(col, CNT, DS);

    run_layer_h(bA, F + O_H, DS + 0 * 256, I, 0, ss.s, ss.fork[0], ss.join[0], nullptr,
                x, eattr, 16, Wn0, We0, b0, a0, row, col,
                F + O_X1, F + O_EA, nullptr, nullptr, 0, nullptr, nullptr, nullptr, nullptr, 1, CNT);
    run_layer_h(bA, F + O_H, DS + 1 * 256, I, 0, ss.s, ss.fork[1], ss.join[1], ss.join[0],
                F + O_X1, F + O_EA, 128, Wn, We, bb, aa, row, col,
                F + O_X1, F + O_EB, nullptr, nullptr, 0, nullptr, nullptr, nullptr, nullptr, 0, nullptr);
    run_layer_h(bA, F + O_H, DS + 2 * 256, I, 0, ss.s, ss.fork[2], ss.join[2], ss.join[1],
                F + O_X1, F + O_EB, 128, Wn + 49152, We + 49152, bb + 768, aa + 1152, row, col,
                F + O_X1, F + O_EA, nullptr, nullptr, 0, nullptr, nullptr, nullptr, nullptr, 0, nullptr);
    run_layer_h(bA, F + O_H, DS + 3 * 256, I, 0, ss.s, ss.fork[3], ss.join[3], ss.join[2],
                F + O_X1, F + O_EA, 128, Wn + 2 * 49152, We + 2 * 49152,
                bb + 2 * 768, aa + 2 * 1152, row, col,
                F + O_X1, F + O_EB, nullptr, nullptr, 0, nullptr, nullptr,
                F + O_EATTN, F + O_ATTNP, 0, nullptr);

    // edgemom on side stream: EB is produced there (join[3] chain), EATTN needs main event
    cudaEventRecord(ss.evEL, 0);
    cudaStreamWaitEvent(ss.s, ss.evEL, 0);
    k_edgemom<<<1024, 128, 0, ss.s>>>(F + O_EB, F + O_EATTN, DS + DS_EDGEMOM);
    k_edgemomfin<<<1, 128, 0, ss.s>>>(DS + DS_EDGEMOM, F + O_MUC, F + O_INVC,
                                      F + O_MUO, F + O_INVO);
    cudaEventRecord(ss.evMom, ss.s);

    k_natt<<<(NN + 7) / 8, 256>>>(F + O_X1, nattW, nattB, F + O_XC, F + O_XO);
    cudaStreamWaitEvent(0, ss.join[3], 0);  // EB complete before branch-A reads it
    cudaMemsetAsync(F + O_GC, 0, 2 * NG * 128 * sizeof(float), 0);

    // fork: branch B (XO) on side stream (already ordered after edgemom), branch A (XC) on main
    cudaEventRecord(ss.evF, 0);
    cudaStreamWaitEvent(ss.s, ss.evF, 0);

    run_layer_h(bB, F + O2_H, DS + 5 * 256, I, ss.s, ss.s, ss.fork[5], ss.join[5], nullptr,
                F + O_XO, F + O_EB, 128, Wn + 4 * 49152, We + 4 * 49152,
                bb + 4 * 768, aa + 4 * 1152, row, col,
                F + O_XO, nullptr, F + O_EATTN, F + O_ATTNP, 1,
                F + O_MUO, F + O_INVO, nullptr, nullptr, 0, nullptr);
    k_segsum<<<(NN * 128 + 255) / 256, 256, 0, ss.s>>>(F + O_XO, batch, F + O_GO);
    cudaEventRecord(ss.evJ, ss.s);

    run_layer_h(bA, F + O_H, DS + 4 * 256, I, 0, 0, ss.fork[4], ss.join[4], ss.evMom,
                F + O_XC, F + O_EB, 128, Wn + 3 * 49152, We + 3 * 49152,
                bb + 3 * 768, aa + 3 * 1152, row, col,
                F + O_XC, nullptr, F + O_EATTN, F + O_ATTNP, 0,
                F + O_MUC, F + O_INVC, nullptr, nullptr, 0, nullptr);
    k_segsum<<<(NN * 128 + 255) / 256, 256>>>(F + O_XC, batch, F + O_GC);

    cudaStreamWaitEvent(0, ss.evJ, 0);
    k_readout<<<3, 128>>>(F + O_GC, F + O_GO, fcW1, fcb1, fcW2, fcb2, (float*)d_out);
}